// round 8
// baseline (speedup 1.0000x reference)
#include <cuda_runtime.h>
#include <cuda_bf16.h>

#define TT 8192
#define DD 64
#define MM 4
#define SEG 4096

// ---------------- scratch (device globals; no allocation) ----------------
__device__ float g_Q [TT * DD];            // Q row-major [t][d]           2MB
__device__ float g_KT[MM * DD * TT];       // K transposed [m][d][t]       8MB
__device__ float g_V2[MM * TT * 2];        // V interleaved [m][t][e]      256KB
__device__ float g_T2[MM * TT];            // t2 per modality (t1 = m=0)
__device__ int   g_idx[MM * TT];           // searchsorted results
__device__ float g_S [MM * DD * TT * 2];   // prefix sums [m][d][t][e]     16MB

// ---------------- packed f32x2 helpers ----------------
__device__ __forceinline__ unsigned long long pack2(float lo, float hi) {
    unsigned long long r;
    asm("mov.b64 %0, {%1, %2};" : "=l"(r) : "f"(lo), "f"(hi));
    return r;
}
__device__ __forceinline__ unsigned long long fma2(unsigned long long a,
                                                   unsigned long long b,
                                                   unsigned long long c) {
    unsigned long long d;
    asm("fma.rn.f32x2 %0, %1, %2, %3;" : "=l"(d) : "l"(a), "l"(b), "l"(c));
    return d;
}
__device__ __forceinline__ float2 unpack2(unsigned long long v) {
    float2 r;
    asm("mov.b64 {%0, %1}, %2;" : "=f"(r.x), "=f"(r.y) : "l"(v));
    return r;
}

// ---------------- Kernel 1: the 5 MLPs (Q and K_0..K_3) + V/t extraction --
__global__ void __launch_bounds__(128) k_mlp(
    const float* __restrict__ X,
    const float* __restrict__ wq_w, const float* __restrict__ wq_b,
    const float* __restrict__ wk_w, const float* __restrict__ wk_b)
{
    __shared__ float As[64 * 65];
    __shared__ float Ws[64 * 64];

    const int tid  = threadIdx.x;
    const int u    = blockIdx.y;                 // 0 -> Q, 1..4 -> K_{u-1}
    const int base = blockIdx.x * 64;
    const int m_in = (u == 0) ? 0 : (u - 1);
    const float* W = (u == 0) ? wq_w : wk_w + (size_t)(u - 1) * 3 * DD * DD;
    const float* B = (u == 0) ? wq_b : wk_b + (size_t)(u - 1) * 3 * DD;

    // load 64x64 A tile transposed into smem: As[d][row]
    {
        const int row = tid >> 1;
        const int hf  = tid & 1;
        const float4* src = (const float4*)(X + ((size_t)m_in * TT + base + row) * DD + hf * 32);
        #pragma unroll
        for (int q = 0; q < 8; q++) {
            float4 v = src[q];
            int d0 = hf * 32 + q * 4;
            As[(d0 + 0) * 65 + row] = v.x;
            As[(d0 + 1) * 65 + row] = v.y;
            As[(d0 + 2) * 65 + row] = v.z;
            As[(d0 + 3) * 65 + row] = v.w;
        }
    }
    __syncthreads();

    // fused prep: V (d=0,1) and times (d=63) from the smem tile (K blocks only)
    if (u >= 1 && tid < 64) {
        const int t = base + tid;
        float2 v;
        v.x = As[0 * 65 + tid];
        v.y = As[1 * 65 + tid];
        ((float2*)g_V2)[(size_t)m_in * TT + t] = v;
        g_T2[(size_t)m_in * TT + t] = As[63 * 65 + tid];
    }

    const int rg = tid & 15;   // rows rg + 16*i, i<4
    const int cg = tid >> 4;   // cols cg*8 .. cg*8+7

    for (int l = 0; l < 3; l++) {
        if (l) __syncthreads();
        {
            const float4* wsrc = (const float4*)(W + (size_t)l * DD * DD);
            #pragma unroll
            for (int q = 0; q < 8; q++)
                ((float4*)Ws)[tid + 128 * q] = wsrc[tid + 128 * q];
        }
        __syncthreads();

        unsigned long long acc2[4][4];
        #pragma unroll
        for (int i = 0; i < 4; i++)
            #pragma unroll
            for (int jp = 0; jp < 4; jp++) acc2[i][jp] = 0ULL;

        #pragma unroll 4
        for (int k = 0; k < 64; k++) {
            unsigned long long a2[4];
            #pragma unroll
            for (int i = 0; i < 4; i++) {
                float a = As[k * 65 + rg + 16 * i];
                a2[i] = pack2(a, a);
            }
            const unsigned long long* wv =
                (const unsigned long long*)(Ws + k * 64 + cg * 8);
            #pragma unroll
            for (int jp = 0; jp < 4; jp++) {
                unsigned long long w2 = wv[jp];
                #pragma unroll
                for (int i = 0; i < 4; i++)
                    acc2[i][jp] = fma2(a2[i], w2, acc2[i][jp]);
            }
        }

        __syncthreads();

        #pragma unroll
        for (int i = 0; i < 4; i++) {
            const int row = rg + 16 * i;
            #pragma unroll
            for (int jp = 0; jp < 4; jp++) {
                float2 v  = unpack2(acc2[i][jp]);
                const int j0 = cg * 8 + jp * 2;
                float2 bb = *(const float2*)(B + l * 64 + j0);
                float o0 = v.x + bb.x;
                float o1 = v.y + bb.y;
                if (l < 2) {
                    o0 = fmaxf(o0, 0.0f);
                    o1 = fmaxf(o1, 0.0f);
                    As[(j0 + 0) * 65 + row] = o0;
                    As[(j0 + 1) * 65 + row] = o1;
                } else if (u == 0) {
                    *(float2*)(g_Q + (size_t)(base + row) * 64 + j0) = make_float2(o0, o1);
                } else {
                    g_KT[(size_t)((u - 1) * 64 + j0    ) * TT + base + row] = o0;
                    g_KT[(size_t)((u - 1) * 64 + j0 + 1) * TT + base + row] = o1;
                }
            }
        }
    }
}

// ---------------- Kernel 2: parallel searchsorted + zero the output -------
__global__ void __launch_bounds__(256) k_idxk(float* __restrict__ out)
{
    const int gid = blockIdx.x * 256 + threadIdx.x;   // [0, MM*TT)
    if (gid < TT)
        ((float2*)out)[gid] = make_float2(0.0f, 0.0f);
    const int t   = gid & (TT - 1);
    const int m   = gid >> 13;
    const float key = g_T2[t];
    const float* arr = g_T2 + (size_t)m * TT;
    int lo = 0, hi = TT;
    while (lo < hi) {
        int mid = (lo + hi) >> 1;
        if (arr[mid] <= key) lo = mid + 1; else hi = mid;
    }
    g_idx[gid] = lo - 1;
}

// ---------------- Kernel 3: fused prefix scan (2 segs, redundant base) ----
// grid = 256 channels * 2 segments, 256 threads, 16 elems/thread.
__global__ void __launch_bounds__(256) k_scanF()
{
    const int ch  = blockIdx.x >> 1;      // m*64+d
    const int seg = blockIdx.x & 1;
    const int m   = ch >> 6;
    const int tid = threadIdx.x;

    const float4* kp = (const float4*)(g_KT + (size_t)ch * TT);
    const float4* vp = (const float4*)(g_V2 + (size_t)m * TT * 2);

    // ---- preceding-segment partial (seg==1): 16 elems at tid*16 ----
    float pre0 = 0.0f, pre1 = 0.0f;
    if (seg) {
        const int pi = tid * 16;
        #pragma unroll
        for (int q = 0; q < 4; q++) {
            float4 k4 = kp[(pi >> 2) + q];
            float4 va = vp[(pi >> 1) + q * 2];
            float4 vb = vp[(pi >> 1) + q * 2 + 1];
            pre0 += k4.x * va.x + k4.y * va.z + k4.z * vb.x + k4.w * vb.z;
            pre1 += k4.x * va.y + k4.y * va.w + k4.z * vb.y + k4.w * vb.w;
        }
    }

    // ---- own 16 elements ----
    const int t0 = seg * SEG + tid * 16;
    float kk[16];
    #pragma unroll
    for (int q = 0; q < 4; q++) {
        float4 k4 = kp[(t0 >> 2) + q];
        kk[q * 4 + 0] = k4.x; kk[q * 4 + 1] = k4.y;
        kk[q * 4 + 2] = k4.z; kk[q * 4 + 3] = k4.w;
    }
    float p0[16], p1[16];
    #pragma unroll
    for (int q = 0; q < 8; q++) {
        float4 v = vp[(t0 >> 1) + q];
        p0[q * 2]     = kk[q * 2]     * v.x;
        p1[q * 2]     = kk[q * 2]     * v.y;
        p0[q * 2 + 1] = kk[q * 2 + 1] * v.z;
        p1[q * 2 + 1] = kk[q * 2 + 1] * v.w;
    }
    #pragma unroll
    for (int e = 1; e < 16; e++) { p0[e] += p0[e - 1]; p1[e] += p1[e - 1]; }

    // ---- block scan of thread totals + block reduce of pre ----
    const int lane = tid & 31, wid = tid >> 5;
    float s0 = p0[15], s1 = p1[15];
    const float t00 = s0, t11 = s1;
    #pragma unroll
    for (int off = 1; off < 32; off <<= 1) {
        float n0 = __shfl_up_sync(0xffffffffu, s0, off);
        float n1 = __shfl_up_sync(0xffffffffu, s1, off);
        if (lane >= off) { s0 += n0; s1 += n1; }
    }
    float pr0 = pre0, pr1 = pre1;
    if (seg) {
        #pragma unroll
        for (int off = 16; off > 0; off >>= 1) {
            pr0 += __shfl_down_sync(0xffffffffu, pr0, off);
            pr1 += __shfl_down_sync(0xffffffffu, pr1, off);
        }
    }
    __shared__ float ws0[8], ws1[8], wp0[8], wp1[8];
    if (lane == 31) { ws0[wid] = s0; ws1[wid] = s1; }
    if (lane == 0)  { wp0[wid] = pr0; wp1[wid] = pr1; }
    __syncthreads();
    float base0 = 0.0f, base1 = 0.0f;
    #pragma unroll
    for (int w = 0; w < 8; w++) {
        base0 += wp0[w]; base1 += wp1[w];
        if (w < wid) { base0 += ws0[w]; base1 += ws1[w]; }
    }
    base0 += s0 - t00;
    base1 += s1 - t11;

    float4* sp = (float4*)(g_S + (size_t)ch * TT * 2);
    #pragma unroll
    for (int q = 0; q < 8; q++) {
        float4 o;
        o.x = base0 + p0[q * 2];     o.y = base1 + p1[q * 2];
        o.z = base0 + p0[q * 2 + 1]; o.w = base1 + p1[q * 2 + 1];
        sp[(t0 >> 1) + q] = o;
    }
}

// ---------------- Kernel 4: gather + contract + atomic accumulate ---------
// grid (T/64, M), 256 threads: (t_local 0..63, dq 0..3 each owning 16 d's).
__global__ void __launch_bounds__(256) k_gath(float* __restrict__ out)
{
    __shared__ float Qs[64 * 65];
    __shared__ float2 red[256];

    const int m   = blockIdx.y;
    const int t0  = blockIdx.x * 64;
    const int tid = threadIdx.x;
    const int lt  = tid & 63;
    const int dq  = tid >> 6;

    {
        const int r = tid >> 2, c4 = tid & 3;
        const float4* src = (const float4*)(g_Q + (size_t)(t0 + r) * 64 + c4 * 16);
        #pragma unroll
        for (int q = 0; q < 4; q++) {
            float4 v = src[q];
            int d0 = c4 * 16 + q * 4;
            Qs[r * 65 + d0 + 0] = v.x;
            Qs[r * 65 + d0 + 1] = v.y;
            Qs[r * 65 + d0 + 2] = v.z;
            Qs[r * 65 + d0 + 3] = v.w;
        }
    }

    const int idx = g_idx[(size_t)m * TT + t0 + lt];
    __syncthreads();

    float a0 = 0.0f, a1 = 0.0f;
    if (idx >= 0) {
        const float2* sp = (const float2*)g_S + (size_t)(m * 64 + dq * 16) * TT + idx;
        #pragma unroll
        for (int dd = 0; dd < 16; dd++) {
            float q  = Qs[lt * 65 + dq * 16 + dd];
            float2 s = sp[(size_t)dd * TT];
            a0 += q * s.x;
            a1 += q * s.y;
        }
    }
    red[tid] = make_float2(a0, a1);
    __syncthreads();

    if (dq == 0) {
        float ax = 0.0f, ay = 0.0f;
        #pragma unroll
        for (int q = 0; q < 4; q++) {
            float2 v = red[lt + 64 * q];
            ax += v.x; ay += v.y;
        }
        atomicAdd(out + (size_t)(t0 + lt) * 2 + 0, ax);
        atomicAdd(out + (size_t)(t0 + lt) * 2 + 1, ay);
    }
}

// ---------------- launch ----------------
extern "C" void kernel_launch(void* const* d_in, const int* in_sizes, int n_in,
                              void* d_out, int out_size)
{
    const float* X    = (const float*)d_in[0];
    const float* wq_w = (const float*)d_in[1];
    const float* wq_b = (const float*)d_in[2];
    const float* wk_w = (const float*)d_in[3];
    const float* wk_b = (const float*)d_in[4];
    float* out = (float*)d_out;

    k_mlp  <<<dim3(TT / 64, 5), 128>>>(X, wq_w, wq_b, wk_w, wk_b);
    k_idxk <<<MM * TT / 256, 256>>>(out);
    k_scanF<<<MM * DD * 2, 256>>>();
    k_gath <<<dim3(TT / 64, MM), 256>>>(out);
}

// round 9
// speedup vs baseline: 1.1670x; 1.1670x over previous
#include <cuda_runtime.h>
#include <cuda_bf16.h>
#include <cstdint>

#define TT 8192
#define DD 64
#define MM 4
#define SEG 4096
#define ASTR 72   // smem k-stride (halves) for A and W tiles (conflict-free)

// ---------------- scratch (device globals; no allocation) ----------------
__device__ float g_Q [TT * DD];            // Q row-major [t][d]           2MB
__device__ float g_KT[MM * DD * TT];       // K transposed [m][d][t]       8MB
__device__ float g_V2[MM * TT * 2];        // V interleaved [m][t][e]      256KB
__device__ float g_T2[MM * TT];            // t2 per modality (t1 = m=0)
__device__ int   g_idx[MM * TT];           // searchsorted results
__device__ float g_S [MM * DD * TT * 2];   // prefix sums [m][d][t][e]     16MB

// ---------------- bf16 split helpers ----------------
__device__ __forceinline__ void split_bf(float f, unsigned short& h, unsigned short& l) {
    __nv_bfloat16 hb = __float2bfloat16(f);
    h = __bfloat16_as_ushort(hb);
    l = __bfloat16_as_ushort(__float2bfloat16(f - __bfloat162float(hb)));
}
__device__ __forceinline__ uint32_t pk(unsigned short a, unsigned short b) {
    return (uint32_t)a | ((uint32_t)b << 16);
}
__device__ __forceinline__ void mma_bf16(float* d, uint32_t a0, uint32_t a1,
                                         uint32_t a2, uint32_t a3,
                                         uint32_t b0, uint32_t b1) {
    asm volatile(
        "mma.sync.aligned.m16n8k16.row.col.f32.bf16.bf16.f32 "
        "{%0,%1,%2,%3},{%4,%5,%6,%7},{%8,%9},{%0,%1,%2,%3};"
        : "+f"(d[0]), "+f"(d[1]), "+f"(d[2]), "+f"(d[3])
        : "r"(a0), "r"(a1), "r"(a2), "r"(a3), "r"(b0), "r"(b1));
}

#define MLP_SMEM ((128 * ASTR * 2 + 64 * ASTR * 2) * 2)   // Ah+Al+Wh+Wl bytes

// ---------------- Kernel 1: 5 MLPs via mma.sync bf16 hi/lo split ----------
// grid (T/128, 5), 256 threads (8 warps), warp w owns rows w*16..w*16+15.
__global__ void __launch_bounds__(256) k_mlp(
    const float* __restrict__ X,
    const float* __restrict__ wq_w, const float* __restrict__ wq_b,
    const float* __restrict__ wk_w, const float* __restrict__ wk_b)
{
    extern __shared__ __align__(16) char sm[];
    __nv_bfloat16* Ah = (__nv_bfloat16*)sm;           // [128][ASTR]
    __nv_bfloat16* Al = Ah + 128 * ASTR;
    __nv_bfloat16* Wh = Al + 128 * ASTR;              // [64][ASTR], layout [n][k]
    __nv_bfloat16* Wl = Wh + 64 * ASTR;
    __shared__ float s_bias[3 * 64];

    const int tid  = threadIdx.x;
    const int w    = tid >> 5;
    const int lane = tid & 31;
    const int g    = lane >> 2;        // 0..7
    const int t2   = (lane & 3) * 2;   // 0,2,4,6
    const int u    = blockIdx.y;
    const int base = blockIdx.x * 128;
    const int m_in = (u == 0) ? 0 : (u - 1);
    const float* W = (u == 0) ? wq_w : wk_w + (size_t)(u - 1) * 3 * DD * DD;
    const float* B = (u == 0) ? wq_b : wk_b + (size_t)(u - 1) * 3 * DD;

    for (int i = tid; i < 192; i += 256) s_bias[i] = B[i];

    // load X tile (128x64), split to bf16 hi/lo, extract V/t2 exactly
    {
        const int row = tid >> 1;
        const int hf  = tid & 1;
        const float4* src = (const float4*)(X + ((size_t)m_in * TT + base + row) * DD + hf * 32);
        #pragma unroll
        for (int q = 0; q < 8; q++) {
            float4 v = src[q];
            if (u >= 1) {
                if (hf == 0 && q == 0)
                    ((float2*)g_V2)[(size_t)m_in * TT + base + row] = make_float2(v.x, v.y);
                if (hf == 1 && q == 7)
                    g_T2[(size_t)m_in * TT + base + row] = v.w;
            }
            const int c0 = hf * 32 + q * 4;
            unsigned short h0, l0, h1, l1, h2, l2, h3, l3;
            split_bf(v.x, h0, l0); split_bf(v.y, h1, l1);
            split_bf(v.z, h2, l2); split_bf(v.w, h3, l3);
            *(uint32_t*)&Ah[row * ASTR + c0]     = pk(h0, h1);
            *(uint32_t*)&Ah[row * ASTR + c0 + 2] = pk(h2, h3);
            *(uint32_t*)&Al[row * ASTR + c0]     = pk(l0, l1);
            *(uint32_t*)&Al[row * ASTR + c0 + 2] = pk(l2, l3);
        }
    }
    __syncthreads();

    for (int l = 0; l < 3; l++) {
        // load W^T (hi/lo): Wh[n][k] = W[k][n]
        const float* Wlay = W + (size_t)l * DD * DD;
        #pragma unroll
        for (int r = 0; r < 16; r++) {
            const int i = tid + 256 * r;
            const int k = i >> 6, n = i & 63;
            unsigned short h, lo;
            split_bf(Wlay[i], h, lo);
            Wh[n * ASTR + k] = __ushort_as_bfloat16(h);
            Wl[n * ASTR + k] = __ushort_as_bfloat16(lo);
        }
        __syncthreads();

        float d[8][4];
        #pragma unroll
        for (int nt = 0; nt < 8; nt++)
            #pragma unroll
            for (int j = 0; j < 4; j++) d[nt][j] = 0.0f;

        #pragma unroll
        for (int ks = 0; ks < 4; ks++) {
            const int ar = (w * 16 + g) * ASTR + ks * 16 + t2;
            uint32_t ah0 = *(uint32_t*)&Ah[ar];
            uint32_t ah1 = *(uint32_t*)&Ah[ar + 8 * ASTR];
            uint32_t ah2 = *(uint32_t*)&Ah[ar + 8];
            uint32_t ah3 = *(uint32_t*)&Ah[ar + 8 * ASTR + 8];
            uint32_t al0 = *(uint32_t*)&Al[ar];
            uint32_t al1 = *(uint32_t*)&Al[ar + 8 * ASTR];
            uint32_t al2 = *(uint32_t*)&Al[ar + 8];
            uint32_t al3 = *(uint32_t*)&Al[ar + 8 * ASTR + 8];
            #pragma unroll
            for (int nt = 0; nt < 8; nt++) {
                const int br = (nt * 8 + g) * ASTR + ks * 16 + t2;
                uint32_t bh0 = *(uint32_t*)&Wh[br];
                uint32_t bh1 = *(uint32_t*)&Wh[br + 8];
                uint32_t bl0 = *(uint32_t*)&Wl[br];
                uint32_t bl1 = *(uint32_t*)&Wl[br + 8];
                mma_bf16(d[nt], ah0, ah1, ah2, ah3, bh0, bh1);
                mma_bf16(d[nt], ah0, ah1, ah2, ah3, bl0, bl1);
                mma_bf16(d[nt], al0, al1, al2, al3, bh0, bh1);
            }
        }
        __syncthreads();   // all W reads done; A rows are warp-private

        const int row0 = w * 16 + g;
        if (l < 2) {
            #pragma unroll
            for (int nt = 0; nt < 8; nt++) {
                const int col = nt * 8 + t2;
                float f0 = fmaxf(d[nt][0] + s_bias[l * 64 + col],     0.0f);
                float f1 = fmaxf(d[nt][1] + s_bias[l * 64 + col + 1], 0.0f);
                float f2 = fmaxf(d[nt][2] + s_bias[l * 64 + col],     0.0f);
                float f3 = fmaxf(d[nt][3] + s_bias[l * 64 + col + 1], 0.0f);
                unsigned short h0, l0, h1, l1, h2, l2, h3, l3;
                split_bf(f0, h0, l0); split_bf(f1, h1, l1);
                split_bf(f2, h2, l2); split_bf(f3, h3, l3);
                *(uint32_t*)&Ah[row0 * ASTR + col]       = pk(h0, h1);
                *(uint32_t*)&Al[row0 * ASTR + col]       = pk(l0, l1);
                *(uint32_t*)&Ah[(row0 + 8) * ASTR + col] = pk(h2, h3);
                *(uint32_t*)&Al[(row0 + 8) * ASTR + col] = pk(l2, l3);
            }
        } else if (u == 0) {
            #pragma unroll
            for (int nt = 0; nt < 8; nt++) {
                const int col = nt * 8 + t2;
                float2 v0 = make_float2(d[nt][0] + s_bias[128 + col],
                                        d[nt][1] + s_bias[128 + col + 1]);
                float2 v1 = make_float2(d[nt][2] + s_bias[128 + col],
                                        d[nt][3] + s_bias[128 + col + 1]);
                *(float2*)(g_Q + (size_t)(base + row0) * 64 + col)     = v0;
                *(float2*)(g_Q + (size_t)(base + row0 + 8) * 64 + col) = v1;
            }
        } else {
            #pragma unroll
            for (int nt = 0; nt < 8; nt++) {
                const int col = nt * 8 + t2;
                const size_t cb = (size_t)((u - 1) * 64 + col) * TT + base;
                g_KT[cb + row0]          = d[nt][0] + s_bias[128 + col];
                g_KT[cb + TT + row0]     = d[nt][1] + s_bias[128 + col + 1];
                g_KT[cb + row0 + 8]      = d[nt][2] + s_bias[128 + col];
                g_KT[cb + TT + row0 + 8] = d[nt][3] + s_bias[128 + col + 1];
            }
        }
    }
}

// ---------------- Kernel 2: parallel searchsorted + zero the output -------
__global__ void __launch_bounds__(256) k_idxk(float* __restrict__ out)
{
    const int gid = blockIdx.x * 256 + threadIdx.x;   // [0, MM*TT)
    if (gid < TT)
        ((float2*)out)[gid] = make_float2(0.0f, 0.0f);
    const int t   = gid & (TT - 1);
    const int m   = gid >> 13;
    const float key = g_T2[t];
    const float* arr = g_T2 + (size_t)m * TT;
    int lo = 0, hi = TT;
    while (lo < hi) {
        int mid = (lo + hi) >> 1;
        if (arr[mid] <= key) lo = mid + 1; else hi = mid;
    }
    g_idx[gid] = lo - 1;
}

// ---------------- Kernel 3: fused prefix scan (2 segs, redundant base) ----
__global__ void __launch_bounds__(256) k_scanF()
{
    const int ch  = blockIdx.x >> 1;      // m*64+d
    const int seg = blockIdx.x & 1;
    const int m   = ch >> 6;
    const int tid = threadIdx.x;

    const float4* kp = (const float4*)(g_KT + (size_t)ch * TT);
    const float4* vp = (const float4*)(g_V2 + (size_t)m * TT * 2);

    float pre0 = 0.0f, pre1 = 0.0f;
    if (seg) {
        const int pi = tid * 16;
        #pragma unroll
        for (int q = 0; q < 4; q++) {
            float4 k4 = kp[(pi >> 2) + q];
            float4 va = vp[(pi >> 1) + q * 2];
            float4 vb = vp[(pi >> 1) + q * 2 + 1];
            pre0 += k4.x * va.x + k4.y * va.z + k4.z * vb.x + k4.w * vb.z;
            pre1 += k4.x * va.y + k4.y * va.w + k4.z * vb.y + k4.w * vb.w;
        }
    }

    const int t0 = seg * SEG + tid * 16;
    float kk[16];
    #pragma unroll
    for (int q = 0; q < 4; q++) {
        float4 k4 = kp[(t0 >> 2) + q];
        kk[q * 4 + 0] = k4.x; kk[q * 4 + 1] = k4.y;
        kk[q * 4 + 2] = k4.z; kk[q * 4 + 3] = k4.w;
    }
    float p0[16], p1[16];
    #pragma unroll
    for (int q = 0; q < 8; q++) {
        float4 v = vp[(t0 >> 1) + q];
        p0[q * 2]     = kk[q * 2]     * v.x;
        p1[q * 2]     = kk[q * 2]     * v.y;
        p0[q * 2 + 1] = kk[q * 2 + 1] * v.z;
        p1[q * 2 + 1] = kk[q * 2 + 1] * v.w;
    }
    #pragma unroll
    for (int e = 1; e < 16; e++) { p0[e] += p0[e - 1]; p1[e] += p1[e - 1]; }

    const int lane = tid & 31, wid = tid >> 5;
    float s0 = p0[15], s1 = p1[15];
    const float t00 = s0, t11 = s1;
    #pragma unroll
    for (int off = 1; off < 32; off <<= 1) {
        float n0 = __shfl_up_sync(0xffffffffu, s0, off);
        float n1 = __shfl_up_sync(0xffffffffu, s1, off);
        if (lane >= off) { s0 += n0; s1 += n1; }
    }
    float pr0 = pre0, pr1 = pre1;
    if (seg) {
        #pragma unroll
        for (int off = 16; off > 0; off >>= 1) {
            pr0 += __shfl_down_sync(0xffffffffu, pr0, off);
            pr1 += __shfl_down_sync(0xffffffffu, pr1, off);
        }
    }
    __shared__ float ws0[8], ws1[8], wp0[8], wp1[8];
    if (lane == 31) { ws0[wid] = s0; ws1[wid] = s1; }
    if (lane == 0)  { wp0[wid] = pr0; wp1[wid] = pr1; }
    __syncthreads();
    float base0 = 0.0f, base1 = 0.0f;
    #pragma unroll
    for (int w = 0; w < 8; w++) {
        base0 += wp0[w]; base1 += wp1[w];
        if (w < wid) { base0 += ws0[w]; base1 += ws1[w]; }
    }
    base0 += s0 - t00;
    base1 += s1 - t11;

    float4* sp = (float4*)(g_S + (size_t)ch * TT * 2);
    #pragma unroll
    for (int q = 0; q < 8; q++) {
        float4 o;
        o.x = base0 + p0[q * 2];     o.y = base1 + p1[q * 2];
        o.z = base0 + p0[q * 2 + 1]; o.w = base1 + p1[q * 2 + 1];
        sp[(t0 >> 1) + q] = o;
    }
}

// ---------------- Kernel 4: gather + contract + atomic accumulate ---------
__global__ void __launch_bounds__(256) k_gath(float* __restrict__ out)
{
    __shared__ float Qs[64 * 65];
    __shared__ float2 red[256];

    const int m   = blockIdx.y;
    const int t0  = blockIdx.x * 64;
    const int tid = threadIdx.x;
    const int lt  = tid & 63;
    const int dq  = tid >> 6;

    {
        const int r = tid >> 2, c4 = tid & 3;
        const float4* src = (const float4*)(g_Q + (size_t)(t0 + r) * 64 + c4 * 16);
        #pragma unroll
        for (int q = 0; q < 4; q++) {
            float4 v = src[q];
            int d0 = c4 * 16 + q * 4;
            Qs[r * 65 + d0 + 0] = v.x;
            Qs[r * 65 + d0 + 1] = v.y;
            Qs[r * 65 + d0 + 2] = v.z;
            Qs[r * 65 + d0 + 3] = v.w;
        }
    }

    const int idx = g_idx[(size_t)m * TT + t0 + lt];
    __syncthreads();

    float a0 = 0.0f, a1 = 0.0f;
    if (idx >= 0) {
        const float2* sp = (const float2*)g_S + (size_t)(m * 64 + dq * 16) * TT + idx;
        #pragma unroll
        for (int dd = 0; dd < 16; dd++) {
            float q  = Qs[lt * 65 + dq * 16 + dd];
            float2 s = sp[(size_t)dd * TT];
            a0 += q * s.x;
            a1 += q * s.y;
        }
    }
    red[tid] = make_float2(a0, a1);
    __syncthreads();

    if (dq == 0) {
        float ax = 0.0f, ay = 0.0f;
        #pragma unroll
        for (int q = 0; q < 4; q++) {
            float2 v = red[lt + 64 * q];
            ax += v.x; ay += v.y;
        }
        atomicAdd(out + (size_t)(t0 + lt) * 2 + 0, ax);
        atomicAdd(out + (size_t)(t0 + lt) * 2 + 1, ay);
    }
}

// ---------------- launch ----------------
extern "C" void kernel_launch(void* const* d_in, const int* in_sizes, int n_in,
                              void* d_out, int out_size)
{
    const float* X    = (const float*)d_in[0];
    const float* wq_w = (const float*)d_in[1];
    const float* wq_b = (const float*)d_in[2];
    const float* wk_w = (const float*)d_in[3];
    const float* wk_b = (const float*)d_in[4];
    float* out = (float*)d_out;

    cudaFuncSetAttribute(k_mlp, cudaFuncAttributeMaxDynamicSharedMemorySize, MLP_SMEM);

    k_mlp  <<<dim3(TT / 128, 5), 256, MLP_SMEM>>>(X, wq_w, wq_b, wk_w, wk_b);
    k_idxk <<<MM * TT / 256, 256>>>(out);
    k_scanF<<<MM * DD * 2, 256>>>();
    k_gath <<<dim3(TT / 64, MM), 256>>>(out);
}

// round 10
// speedup vs baseline: 1.2535x; 1.0742x over previous
#include <cuda_runtime.h>
#include <cuda_bf16.h>
#include <cstdint>

#define TT 8192
#define DD 64
#define MM 4
#define SEG 4096
#define ASTR 72   // smem k-stride (halves) for A and W tiles (conflict-free)

// ---------------- scratch (device globals; no allocation) ----------------
__device__ float g_Q [TT * DD];            // Q row-major [t][d]           2MB
__device__ float g_KT[MM * DD * TT];       // K transposed [m][d][t]       8MB
__device__ float g_V2[MM * TT * 2];        // V interleaved [m][t][e]      256KB
__device__ float g_T2[MM * TT];            // t2 per modality (t1 = m=0)
__device__ int   g_idx[MM * TT];           // searchsorted results
__device__ float g_S [MM * DD * TT * 2];   // prefix sums [m][d][t][e]     16MB

// ---------------- bf16 split helpers ----------------
__device__ __forceinline__ void split_bf(float f, unsigned short& h, unsigned short& l) {
    __nv_bfloat16 hb = __float2bfloat16(f);
    h = __bfloat16_as_ushort(hb);
    l = __bfloat16_as_ushort(__float2bfloat16(f - __bfloat162float(hb)));
}
__device__ __forceinline__ uint32_t pk(unsigned short a, unsigned short b) {
    return (uint32_t)a | ((uint32_t)b << 16);
}
__device__ __forceinline__ void mma_bf16(float* d, uint32_t a0, uint32_t a1,
                                         uint32_t a2, uint32_t a3,
                                         uint32_t b0, uint32_t b1) {
    asm volatile(
        "mma.sync.aligned.m16n8k16.row.col.f32.bf16.bf16.f32 "
        "{%0,%1,%2,%3},{%4,%5,%6,%7},{%8,%9},{%0,%1,%2,%3};"
        : "+f"(d[0]), "+f"(d[1]), "+f"(d[2]), "+f"(d[3])
        : "r"(a0), "r"(a1), "r"(a2), "r"(a3), "r"(b0), "r"(b1));
}

#define MLP_SMEM ((128 * ASTR * 2 + 64 * ASTR * 2) * 2)   // Ah+Al+Wh+Wl bytes

// ---------------- Kernel 1: 5 MLPs via mma.sync bf16 hi/lo split ----------
// grid (T/128, 5), 256 threads (8 warps), warp w owns rows w*16..w*16+15.
__global__ void __launch_bounds__(256) k_mlp(
    const float* __restrict__ X,
    const float* __restrict__ wq_w, const float* __restrict__ wq_b,
    const float* __restrict__ wk_w, const float* __restrict__ wk_b)
{
    extern __shared__ __align__(16) char sm[];
    __nv_bfloat16* Ah = (__nv_bfloat16*)sm;           // [128][ASTR]
    __nv_bfloat16* Al = Ah + 128 * ASTR;
    __nv_bfloat16* Wh = Al + 128 * ASTR;              // [64][ASTR], layout [n][k]
    __nv_bfloat16* Wl = Wh + 64 * ASTR;
    float* St = (float*)sm;                           // staging (reuses Ah+Al, 36864B)
    __shared__ float s_bias[3 * 64];

    const int tid  = threadIdx.x;
    const int w    = tid >> 5;
    const int lane = tid & 31;
    const int g    = lane >> 2;        // 0..7
    const int t2   = (lane & 3) * 2;   // 0,2,4,6
    const int u    = blockIdx.y;
    const int base = blockIdx.x * 128;
    const int m_in = (u == 0) ? 0 : (u - 1);
    const float* W = (u == 0) ? wq_w : wk_w + (size_t)(u - 1) * 3 * DD * DD;
    const float* B = (u == 0) ? wq_b : wk_b + (size_t)(u - 1) * 3 * DD;

    for (int i = tid; i < 192; i += 256) s_bias[i] = B[i];

    // load X tile (128x64), split to bf16 hi/lo, extract V/t2 exactly
    {
        const int row = tid >> 1;
        const int hf  = tid & 1;
        const float4* src = (const float4*)(X + ((size_t)m_in * TT + base + row) * DD + hf * 32);
        #pragma unroll
        for (int q = 0; q < 8; q++) {
            float4 v = src[q];
            if (u >= 1) {
                if (hf == 0 && q == 0)
                    ((float2*)g_V2)[(size_t)m_in * TT + base + row] = make_float2(v.x, v.y);
                if (hf == 1 && q == 7)
                    g_T2[(size_t)m_in * TT + base + row] = v.w;
            }
            const int c0 = hf * 32 + q * 4;
            unsigned short h0, l0, h1, l1, h2, l2, h3, l3;
            split_bf(v.x, h0, l0); split_bf(v.y, h1, l1);
            split_bf(v.z, h2, l2); split_bf(v.w, h3, l3);
            *(uint32_t*)&Ah[row * ASTR + c0]     = pk(h0, h1);
            *(uint32_t*)&Ah[row * ASTR + c0 + 2] = pk(h2, h3);
            *(uint32_t*)&Al[row * ASTR + c0]     = pk(l0, l1);
            *(uint32_t*)&Al[row * ASTR + c0 + 2] = pk(l2, l3);
        }
    }
    __syncthreads();

    for (int l = 0; l < 3; l++) {
        // load W^T (hi/lo): Wh[n][k] = W[k][n]
        const float* Wlay = W + (size_t)l * DD * DD;
        #pragma unroll
        for (int r = 0; r < 16; r++) {
            const int i = tid + 256 * r;
            const int k = i >> 6, n = i & 63;
            unsigned short h, lo;
            split_bf(Wlay[i], h, lo);
            Wh[n * ASTR + k] = __ushort_as_bfloat16(h);
            Wl[n * ASTR + k] = __ushort_as_bfloat16(lo);
        }
        __syncthreads();

        float d[8][4];
        #pragma unroll
        for (int nt = 0; nt < 8; nt++)
            #pragma unroll
            for (int j = 0; j < 4; j++) d[nt][j] = 0.0f;

        #pragma unroll
        for (int ks = 0; ks < 4; ks++) {
            const int ar = (w * 16 + g) * ASTR + ks * 16 + t2;
            uint32_t ah0 = *(uint32_t*)&Ah[ar];
            uint32_t ah1 = *(uint32_t*)&Ah[ar + 8 * ASTR];
            uint32_t ah2 = *(uint32_t*)&Ah[ar + 8];
            uint32_t ah3 = *(uint32_t*)&Ah[ar + 8 * ASTR + 8];
            uint32_t al0 = *(uint32_t*)&Al[ar];
            uint32_t al1 = *(uint32_t*)&Al[ar + 8 * ASTR];
            uint32_t al2 = *(uint32_t*)&Al[ar + 8];
            uint32_t al3 = *(uint32_t*)&Al[ar + 8 * ASTR + 8];
            #pragma unroll
            for (int nt = 0; nt < 8; nt++) {
                const int br = (nt * 8 + g) * ASTR + ks * 16 + t2;
                uint32_t bh0 = *(uint32_t*)&Wh[br];
                uint32_t bh1 = *(uint32_t*)&Wh[br + 8];
                uint32_t bl0 = *(uint32_t*)&Wl[br];
                uint32_t bl1 = *(uint32_t*)&Wl[br + 8];
                mma_bf16(d[nt], ah0, ah1, ah2, ah3, bh0, bh1);
                mma_bf16(d[nt], ah0, ah1, ah2, ah3, bl0, bl1);
                mma_bf16(d[nt], al0, al1, al2, al3, bh0, bh1);
            }
        }
        __syncthreads();   // all warps done reading A/W smem

        const int row0 = w * 16 + g;
        if (l < 2) {
            #pragma unroll
            for (int nt = 0; nt < 8; nt++) {
                const int col = nt * 8 + t2;
                float f0 = fmaxf(d[nt][0] + s_bias[l * 64 + col],     0.0f);
                float f1 = fmaxf(d[nt][1] + s_bias[l * 64 + col + 1], 0.0f);
                float f2 = fmaxf(d[nt][2] + s_bias[l * 64 + col],     0.0f);
                float f3 = fmaxf(d[nt][3] + s_bias[l * 64 + col + 1], 0.0f);
                unsigned short h0, l0, h1, l1, h2, l2, h3, l3;
                split_bf(f0, h0, l0); split_bf(f1, h1, l1);
                split_bf(f2, h2, l2); split_bf(f3, h3, l3);
                *(uint32_t*)&Ah[row0 * ASTR + col]       = pk(h0, h1);
                *(uint32_t*)&Al[row0 * ASTR + col]       = pk(l0, l1);
                *(uint32_t*)&Ah[(row0 + 8) * ASTR + col] = pk(h2, h3);
                *(uint32_t*)&Al[(row0 + 8) * ASTR + col] = pk(l2, l3);
            }
        } else if (u == 0) {
            // stage St[row][col] (stride 72), then coalesced float4 out
            #pragma unroll
            for (int nt = 0; nt < 8; nt++) {
                const int col = nt * 8 + t2;
                St[row0 * 72 + col]           = d[nt][0] + s_bias[128 + col];
                St[row0 * 72 + col + 1]       = d[nt][1] + s_bias[128 + col + 1];
                St[(row0 + 8) * 72 + col]     = d[nt][2] + s_bias[128 + col];
                St[(row0 + 8) * 72 + col + 1] = d[nt][3] + s_bias[128 + col + 1];
            }
            __syncthreads();
            const int row = tid >> 1, c0 = (tid & 1) * 32;
            #pragma unroll
            for (int q = 0; q < 8; q++) {
                float4 v = *(float4*)&St[row * 72 + c0 + q * 4];
                *(float4*)&g_Q[(size_t)(base + row) * 64 + c0 + q * 4] = v;
            }
        } else {
            // stage St[col][row] (stride 132), then coalesced float4 out
            #pragma unroll
            for (int nt = 0; nt < 8; nt++) {
                const int col = nt * 8 + t2;
                St[col * 132 + row0]           = d[nt][0] + s_bias[128 + col];
                St[(col + 1) * 132 + row0]     = d[nt][1] + s_bias[128 + col + 1];
                St[col * 132 + row0 + 8]       = d[nt][2] + s_bias[128 + col];
                St[(col + 1) * 132 + row0 + 8] = d[nt][3] + s_bias[128 + col + 1];
            }
            __syncthreads();
            const int col = tid >> 2, l4 = tid & 3;
            const size_t cb = (size_t)((u - 1) * 64 + col) * TT + base;
            #pragma unroll
            for (int q = 0; q < 8; q++) {
                const int row = l4 * 4 + q * 16;
                float4 v = *(float4*)&St[col * 132 + row];
                *(float4*)&g_KT[cb + row] = v;
            }
        }
    }
}

// ---------------- Kernel 2: fused scan (blocks 0..511) + searchsorted (512..639)
__global__ void __launch_bounds__(256) k_scanIdx(float* __restrict__ out)
{
    const int tid = threadIdx.x;

    if (blockIdx.x >= 512) {
        // searchsorted + zero the output
        const int gid = (blockIdx.x - 512) * 256 + tid;   // [0, MM*TT)
        if (gid < TT)
            ((float2*)out)[gid] = make_float2(0.0f, 0.0f);
        const int t = gid & (TT - 1);
        const int m = gid >> 13;
        const float key = g_T2[t];
        const float* arr = g_T2 + (size_t)m * TT;
        int lo = 0, hi = TT;
        while (lo < hi) {
            int mid = (lo + hi) >> 1;
            if (arr[mid] <= key) lo = mid + 1; else hi = mid;
        }
        g_idx[gid] = lo - 1;
        return;
    }

    const int ch  = blockIdx.x >> 1;      // m*64+d
    const int seg = blockIdx.x & 1;
    const int m   = ch >> 6;

    const float4* kp = (const float4*)(g_KT + (size_t)ch * TT);
    const float4* vp = (const float4*)(g_V2 + (size_t)m * TT * 2);

    float pre0 = 0.0f, pre1 = 0.0f;
    if (seg) {
        const int pi = tid * 16;
        #pragma unroll
        for (int q = 0; q < 4; q++) {
            float4 k4 = kp[(pi >> 2) + q];
            float4 va = vp[(pi >> 1) + q * 2];
            float4 vb = vp[(pi >> 1) + q * 2 + 1];
            pre0 += k4.x * va.x + k4.y * va.z + k4.z * vb.x + k4.w * vb.z;
            pre1 += k4.x * va.y + k4.y * va.w + k4.z * vb.y + k4.w * vb.w;
        }
    }

    const int t0 = seg * SEG + tid * 16;
    float kk[16];
    #pragma unroll
    for (int q = 0; q < 4; q++) {
        float4 k4 = kp[(t0 >> 2) + q];
        kk[q * 4 + 0] = k4.x; kk[q * 4 + 1] = k4.y;
        kk[q * 4 + 2] = k4.z; kk[q * 4 + 3] = k4.w;
    }
    float p0[16], p1[16];
    #pragma unroll
    for (int q = 0; q < 8; q++) {
        float4 v = vp[(t0 >> 1) + q];
        p0[q * 2]     = kk[q * 2]     * v.x;
        p1[q * 2]     = kk[q * 2]     * v.y;
        p0[q * 2 + 1] = kk[q * 2 + 1] * v.z;
        p1[q * 2 + 1] = kk[q * 2 + 1] * v.w;
    }
    #pragma unroll
    for (int e = 1; e < 16; e++) { p0[e] += p0[e - 1]; p1[e] += p1[e - 1]; }

    const int lane = tid & 31, wid = tid >> 5;
    float s0 = p0[15], s1 = p1[15];
    const float t00 = s0, t11 = s1;
    #pragma unroll
    for (int off = 1; off < 32; off <<= 1) {
        float n0 = __shfl_up_sync(0xffffffffu, s0, off);
        float n1 = __shfl_up_sync(0xffffffffu, s1, off);
        if (lane >= off) { s0 += n0; s1 += n1; }
    }
    float pr0 = pre0, pr1 = pre1;
    if (seg) {
        #pragma unroll
        for (int off = 16; off > 0; off >>= 1) {
            pr0 += __shfl_down_sync(0xffffffffu, pr0, off);
            pr1 += __shfl_down_sync(0xffffffffu, pr1, off);
        }
    }
    __shared__ float ws0[8], ws1[8], wp0[8], wp1[8];
    if (lane == 31) { ws0[wid] = s0; ws1[wid] = s1; }
    if (lane == 0)  { wp0[wid] = pr0; wp1[wid] = pr1; }
    __syncthreads();
    float base0 = 0.0f, base1 = 0.0f;
    #pragma unroll
    for (int w = 0; w < 8; w++) {
        base0 += wp0[w]; base1 += wp1[w];
        if (w < wid) { base0 += ws0[w]; base1 += ws1[w]; }
    }
    base0 += s0 - t00;
    base1 += s1 - t11;

    float4* sp = (float4*)(g_S + (size_t)ch * TT * 2);
    #pragma unroll
    for (int q = 0; q < 8; q++) {
        float4 o;
        o.x = base0 + p0[q * 2];     o.y = base1 + p1[q * 2];
        o.z = base0 + p0[q * 2 + 1]; o.w = base1 + p1[q * 2 + 1];
        sp[(t0 >> 1) + q] = o;
    }
}

// ---------------- Kernel 3: gather + contract + atomic accumulate ---------
__global__ void __launch_bounds__(256) k_gath(float* __restrict__ out)
{
    __shared__ float Qs[64 * 65];
    __shared__ float2 red[256];

    const int m   = blockIdx.y;
    const int t0  = blockIdx.x * 64;
    const int tid = threadIdx.x;
    const int lt  = tid & 63;
    const int dq  = tid >> 6;

    {
        const int r = tid >> 2, c4 = tid & 3;
        const float4* src = (const float4*)(g_Q + (size_t)(t0 + r) * 64 + c4 * 16);
        #pragma unroll
        for (int q = 0; q < 4; q++) {
            float4 v = src[q];
            int d0 = c4 * 16 + q * 4;
            Qs[r * 65 + d0 + 0] = v.x;
            Qs[r * 65 + d0 + 1] = v.y;
            Qs[r * 65 + d0 + 2] = v.z;
            Qs[r * 65 + d0 + 3] = v.w;
        }
    }

    const int idx = g_idx[(size_t)m * TT + t0 + lt];
    __syncthreads();

    float a0 = 0.0f, a1 = 0.0f;
    if (idx >= 0) {
        const float2* sp = (const float2*)g_S + (size_t)(m * 64 + dq * 16) * TT + idx;
        #pragma unroll
        for (int dd = 0; dd < 16; dd++) {
            float q  = Qs[lt * 65 + dq * 16 + dd];
            float2 s = sp[(size_t)dd * TT];
            a0 += q * s.x;
            a1 += q * s.y;
        }
    }
    red[tid] = make_float2(a0, a1);
    __syncthreads();

    if (dq == 0) {
        float ax = 0.0f, ay = 0.0f;
        #pragma unroll
        for (int q = 0; q < 4; q++) {
            float2 v = red[lt + 64 * q];
            ax += v.x; ay += v.y;
        }
        atomicAdd(out + (size_t)(t0 + lt) * 2 + 0, ax);
        atomicAdd(out + (size_t)(t0 + lt) * 2 + 1, ay);
    }
}

// ---------------- launch ----------------
extern "C" void kernel_launch(void* const* d_in, const int* in_sizes, int n_in,
                              void* d_out, int out_size)
{
    const float* X    = (const float*)d_in[0];
    const float* wq_w = (const float*)d_in[1];
    const float* wq_b = (const float*)d_in[2];
    const float* wk_w = (const float*)d_in[3];
    const float* wk_b = (const float*)d_in[4];
    float* out = (float*)d_out;

    cudaFuncSetAttribute(k_mlp, cudaFuncAttributeMaxDynamicSharedMemorySize, MLP_SMEM);

    k_mlp    <<<dim3(TT / 128, 5), 256, MLP_SMEM>>>(X, wq_w, wq_b, wk_w, wk_b);
    k_scanIdx<<<512 + 128, 256>>>(out);
    k_gath   <<<dim3(TT / 64, MM), 256>>>(out);
}

// round 11
// speedup vs baseline: 1.3645x; 1.0885x over previous
#include <cuda_runtime.h>
#include <cuda_bf16.h>
#include <cstdint>

#define TT 8192
#define DD 64
#define MM 4
#define SEG 4096

// ---------------- scratch (device globals; no allocation) ----------------
__device__ float g_Q [TT * DD];            // Q row-major [t][d]           2MB
__device__ float g_KT[MM * DD * TT];       // K transposed [m][d][t]       8MB
__device__ float g_V2[MM * TT * 2];        // V interleaved [m][t][e]      256KB
__device__ float g_T2[MM * TT];            // t2 per modality (t1 = m=0)
__device__ int   g_idx[MM * TT];           // searchsorted results
__device__ float g_S [MM * DD * TT * 2];   // prefix sums [m][d][t][e]     16MB

// ---------------- bf16 split helpers ----------------
__device__ __forceinline__ uint32_t pk(unsigned short a, unsigned short b) {
    return (uint32_t)a | ((uint32_t)b << 16);
}
__device__ __forceinline__ void split2(float fx, float fy, uint32_t& h, uint32_t& l) {
    __nv_bfloat16 h0 = __float2bfloat16(fx), h1 = __float2bfloat16(fy);
    h = pk(__bfloat16_as_ushort(h0), __bfloat16_as_ushort(h1));
    l = pk(__bfloat16_as_ushort(__float2bfloat16(fx - __bfloat162float(h0))),
           __bfloat16_as_ushort(__float2bfloat16(fy - __bfloat162float(h1))));
}
__device__ __forceinline__ void mma_bf16(float* d, uint32_t a0, uint32_t a1,
                                         uint32_t a2, uint32_t a3,
                                         uint32_t b0, uint32_t b1) {
    asm volatile(
        "mma.sync.aligned.m16n8k16.row.col.f32.bf16.bf16.f32 "
        "{%0,%1,%2,%3},{%4,%5,%6,%7},{%8,%9},{%0,%1,%2,%3};"
        : "+f"(d[0]), "+f"(d[1]), "+f"(d[2]), "+f"(d[3])
        : "r"(a0), "r"(a1), "r"(a2), "r"(a3), "r"(b0), "r"(b1));
}

// AFRAG: [h/l][ks][w][lane] uint4 = (a0, a2, a1, a3)  -> 2048 uint4 = 32KB
// WFRAG: [ks][nt][lane]     uint4 = (bh0,bh1,bl0,bl1) -> 1024 uint4 = 16KB
#define MLP_SMEM (3072 * 16)

// ---------------- Kernel 1: 5 MLPs, fragment-resident smem -----------------
// grid (T/128, 5), 256 threads (8 warps); warp w owns rows w*16 .. w*16+15.
__global__ void __launch_bounds__(256, 3) k_mlp(
    const float* __restrict__ X,
    const float* __restrict__ wq_w, const float* __restrict__ wq_b,
    const float* __restrict__ wk_w, const float* __restrict__ wk_b)
{
    extern __shared__ __align__(16) uint4 sm4[];
    uint4* A4 = sm4;            // [h][ks][w][lane]
    uint4* W4 = sm4 + 2048;     // [ks][nt][lane]
    float* St = (float*)sm4;    // final-layer staging (reuses everything)
    __shared__ float s_bias[3 * 64];

    const int tid  = threadIdx.x;
    const int w    = tid >> 5;
    const int lane = tid & 31;
    const int g    = lane >> 2;   // 0..7
    const int q    = lane & 3;    // 0..3
    const int u    = blockIdx.y;
    const int base = blockIdx.x * 128;
    const int m_in = (u == 0) ? 0 : (u - 1);
    const float* W = (u == 0) ? wq_w : wk_w + (size_t)(u - 1) * 3 * DD * DD;
    const float* B = (u == 0) ? wq_b : wk_b + (size_t)(u - 1) * 3 * DD;

    for (int i = tid; i < 192; i += 256) s_bias[i] = B[i];

    // ---- initial A fragments straight from X (warp-private region) ----
    {
        const int r0 = base + w * 16 + g;
        const float* x0 = X + ((size_t)m_in * TT + r0) * DD;
        const float* x1 = x0 + 8 * DD;
        #pragma unroll
        for (int ks = 0; ks < 4; ks++) {
            float2 a0 = *(const float2*)(x0 + ks * 16 + 2 * q);
            float2 a2 = *(const float2*)(x0 + ks * 16 + 8 + 2 * q);
            float2 a1 = *(const float2*)(x1 + ks * 16 + 2 * q);
            float2 a3 = *(const float2*)(x1 + ks * 16 + 8 + 2 * q);
            if (u >= 1) {
                if (ks == 0 && q == 0) {
                    ((float2*)g_V2)[(size_t)m_in * TT + r0]     = a0;
                    ((float2*)g_V2)[(size_t)m_in * TT + r0 + 8] = a1;
                }
                if (ks == 3 && q == 3) {            // k = 63 lives in a2.y/a3.y
                    g_T2[(size_t)m_in * TT + r0]     = a2.y;
                    g_T2[(size_t)m_in * TT + r0 + 8] = a3.y;
                }
            }
            uint4 vh, vl;
            split2(a0.x, a0.y, vh.x, vl.x);
            split2(a2.x, a2.y, vh.y, vl.y);
            split2(a1.x, a1.y, vh.z, vl.z);
            split2(a3.x, a3.y, vh.w, vl.w);
            A4[(ks * 8 + w) * 32 + lane]        = vh;
            A4[((4 + ks) * 8 + w) * 32 + lane]  = vl;
        }
    }

    for (int l = 0; l < 3; l++) {
        __syncthreads();   // prior-layer WFRAG reads complete

        // ---- produce WFRAG: warp w fills nt=w; thread covers n=w*8+g, k-pair q
        {
            const float* Wlay = W + (size_t)l * DD * DD;
            const int n = w * 8 + g;
            #pragma unroll
            for (int ks = 0; ks < 4; ks++) {
                const float* wp = Wlay + (ks * 16 + 2 * q) * 64 + n;
                float b00 = wp[0],      b01 = wp[64];
                float b10 = wp[8 * 64], b11 = wp[9 * 64];
                uint4 v;
                split2(b00, b01, v.x, v.z);
                split2(b10, b11, v.y, v.w);
                W4[(ks * 8 + w) * 32 + lane] = v;
            }
        }
        __syncthreads();

        // ---- MMA: 4 ks x 8 nt x 3 (hh, hl, lh) ----
        float d[8][4];
        #pragma unroll
        for (int nt = 0; nt < 8; nt++)
            #pragma unroll
            for (int j = 0; j < 4; j++) d[nt][j] = 0.0f;

        #pragma unroll
        for (int ks = 0; ks < 4; ks++) {
            uint4 ah = A4[(ks * 8 + w) * 32 + lane];
            uint4 al = A4[((4 + ks) * 8 + w) * 32 + lane];
            #pragma unroll
            for (int nt = 0; nt < 8; nt++) {
                uint4 b = W4[(ks * 8 + nt) * 32 + lane];
                mma_bf16(d[nt], ah.x, ah.z, ah.y, ah.w, b.x, b.y);
                mma_bf16(d[nt], ah.x, ah.z, ah.y, ah.w, b.z, b.w);
                mma_bf16(d[nt], al.x, al.z, al.y, al.w, b.x, b.y);
            }
        }

        if (l < 2) {
            // ---- epilogue -> next layer's A fragments (warp-private, no sync)
            #pragma unroll
            for (int ksn = 0; ksn < 4; ksn++) {
                const int nt0 = 2 * ksn, nt1 = nt0 + 1;
                const int c0 = nt0 * 8 + 2 * q, c1 = nt1 * 8 + 2 * q;
                float f0x = fmaxf(d[nt0][0] + s_bias[l * 64 + c0],     0.0f);
                float f0y = fmaxf(d[nt0][1] + s_bias[l * 64 + c0 + 1], 0.0f);
                float f1x = fmaxf(d[nt1][0] + s_bias[l * 64 + c1],     0.0f);
                float f1y = fmaxf(d[nt1][1] + s_bias[l * 64 + c1 + 1], 0.0f);
                float f2x = fmaxf(d[nt0][2] + s_bias[l * 64 + c0],     0.0f);
                float f2y = fmaxf(d[nt0][3] + s_bias[l * 64 + c0 + 1], 0.0f);
                float f3x = fmaxf(d[nt1][2] + s_bias[l * 64 + c1],     0.0f);
                float f3y = fmaxf(d[nt1][3] + s_bias[l * 64 + c1 + 1], 0.0f);
                uint4 vh, vl;
                split2(f0x, f0y, vh.x, vl.x);
                split2(f1x, f1y, vh.y, vl.y);
                split2(f2x, f2y, vh.z, vl.z);
                split2(f3x, f3y, vh.w, vl.w);
                A4[(ksn * 8 + w) * 32 + lane]       = vh;
                A4[((4 + ksn) * 8 + w) * 32 + lane] = vl;
            }
        } else {
            __syncthreads();   // everyone done with A4/W4 before St overwrite
            const int row0 = w * 16 + g;
            if (u == 0) {
                // stage row-major [row][72], then coalesced float4 out
                #pragma unroll
                for (int nt = 0; nt < 8; nt++) {
                    const int col = nt * 8 + 2 * q;
                    St[row0 * 72 + col]           = d[nt][0] + s_bias[128 + col];
                    St[row0 * 72 + col + 1]       = d[nt][1] + s_bias[128 + col + 1];
                    St[(row0 + 8) * 72 + col]     = d[nt][2] + s_bias[128 + col];
                    St[(row0 + 8) * 72 + col + 1] = d[nt][3] + s_bias[128 + col + 1];
                }
                __syncthreads();
                const int row = tid >> 1, c0 = (tid & 1) * 32;
                #pragma unroll
                for (int qq = 0; qq < 8; qq++) {
                    float4 v = *(float4*)&St[row * 72 + c0 + qq * 4];
                    *(float4*)&g_Q[(size_t)(base + row) * 64 + c0 + qq * 4] = v;
                }
            } else {
                // stage col-major [col][132], then coalesced float4 out
                #pragma unroll
                for (int nt = 0; nt < 8; nt++) {
                    const int col = nt * 8 + 2 * q;
                    St[col * 132 + row0]           = d[nt][0] + s_bias[128 + col];
                    St[(col + 1) * 132 + row0]     = d[nt][1] + s_bias[128 + col + 1];
                    St[col * 132 + row0 + 8]       = d[nt][2] + s_bias[128 + col];
                    St[(col + 1) * 132 + row0 + 8] = d[nt][3] + s_bias[128 + col + 1];
                }
                __syncthreads();
                const int col = tid >> 2, l4 = tid & 3;
                const size_t cb = (size_t)((u - 1) * 64 + col) * TT + base;
                #pragma unroll
                for (int qq = 0; qq < 8; qq++) {
                    const int row = l4 * 4 + qq * 16;
                    float4 v = *(float4*)&St[col * 132 + row];
                    *(float4*)&g_KT[cb + row] = v;
                }
            }
        }
    }
}

// ---------------- Kernel 2: fused scan (blocks 0..511) + searchsorted (512..639)
__global__ void __launch_bounds__(256) k_scanIdx(float* __restrict__ out)
{
    const int tid = threadIdx.x;

    if (blockIdx.x >= 512) {
        const int gid = (blockIdx.x - 512) * 256 + tid;   // [0, MM*TT)
        if (gid < TT)
            ((float2*)out)[gid] = make_float2(0.0f, 0.0f);
        const int t = gid & (TT - 1);
        const int m = gid >> 13;
        const float key = g_T2[t];
        const float* arr = g_T2 + (size_t)m * TT;
        int lo = 0, hi = TT;
        while (lo < hi) {
            int mid = (lo + hi) >> 1;
            if (arr[mid] <= key) lo = mid + 1; else hi = mid;
        }
        g_idx[gid] = lo - 1;
        return;
    }

    const int ch  = blockIdx.x >> 1;      // m*64+d
    const int seg = blockIdx.x & 1;
    const int m   = ch >> 6;

    const float4* kp = (const float4*)(g_KT + (size_t)ch * TT);
    const float4* vp = (const float4*)(g_V2 + (size_t)m * TT * 2);

    float pre0 = 0.0f, pre1 = 0.0f;
    if (seg) {
        const int pi = tid * 16;
        #pragma unroll
        for (int q = 0; q < 4; q++) {
            float4 k4 = kp[(pi >> 2) + q];
            float4 va = vp[(pi >> 1) + q * 2];
            float4 vb = vp[(pi >> 1) + q * 2 + 1];
            pre0 += k4.x * va.x + k4.y * va.z + k4.z * vb.x + k4.w * vb.z;
            pre1 += k4.x * va.y + k4.y * va.w + k4.z * vb.y + k4.w * vb.w;
        }
    }

    const int t0 = seg * SEG + tid * 16;
    float kk[16];
    #pragma unroll
    for (int q = 0; q < 4; q++) {
        float4 k4 = kp[(t0 >> 2) + q];
        kk[q * 4 + 0] = k4.x; kk[q * 4 + 1] = k4.y;
        kk[q * 4 + 2] = k4.z; kk[q * 4 + 3] = k4.w;
    }
    float p0[16], p1[16];
    #pragma unroll
    for (int q = 0; q < 8; q++) {
        float4 v = vp[(t0 >> 1) + q];
        p0[q * 2]     = kk[q * 2]     * v.x;
        p1[q * 2]     = kk[q * 2]     * v.y;
        p0[q * 2 + 1] = kk[q * 2 + 1] * v.z;
        p1[q * 2 + 1] = kk[q * 2 + 1] * v.w;
    }
    #pragma unroll
    for (int e = 1; e < 16; e++) { p0[e] += p0[e - 1]; p1[e] += p1[e - 1]; }

    const int lane = tid & 31, wid = tid >> 5;
    float s0 = p0[15], s1 = p1[15];
    const float t00 = s0, t11 = s1;
    #pragma unroll
    for (int off = 1; off < 32; off <<= 1) {
        float n0 = __shfl_up_sync(0xffffffffu, s0, off);
        float n1 = __shfl_up_sync(0xffffffffu, s1, off);
        if (lane >= off) { s0 += n0; s1 += n1; }
    }
    float pr0 = pre0, pr1 = pre1;
    if (seg) {
        #pragma unroll
        for (int off = 16; off > 0; off >>= 1) {
            pr0 += __shfl_down_sync(0xffffffffu, pr0, off);
            pr1 += __shfl_down_sync(0xffffffffu, pr1, off);
        }
    }
    __shared__ float ws0[8], ws1[8], wp0[8], wp1[8];
    if (lane == 31) { ws0[wid] = s0; ws1[wid] = s1; }
    if (lane == 0)  { wp0[wid] = pr0; wp1[wid] = pr1; }
    __syncthreads();
    float base0 = 0.0f, base1 = 0.0f;
    #pragma unroll
    for (int w = 0; w < 8; w++) {
        base0 += wp0[w]; base1 += wp1[w];
        if (w < wid) { base0 += ws0[w]; base1 += ws1[w]; }
    }
    base0 += s0 - t00;
    base1 += s1 - t11;

    float4* sp = (float4*)(g_S + (size_t)ch * TT * 2);
    #pragma unroll
    for (int q = 0; q < 8; q++) {
        float4 o;
        o.x = base0 + p0[q * 2];     o.y = base1 + p1[q * 2];
        o.z = base0 + p0[q * 2 + 1]; o.w = base1 + p1[q * 2 + 1];
        sp[(t0 >> 1) + q] = o;
    }
}

// ---------------- Kernel 3: gather + contract + atomic accumulate ---------
__global__ void __launch_bounds__(256) k_gath(float* __restrict__ out)
{
    __shared__ float Qs[64 * 65];
    __shared__ float2 red[256];

    const int m   = blockIdx.y;
    const int t0  = blockIdx.x * 64;
    const int tid = threadIdx.x;
    const int lt  = tid & 63;
    const int dq  = tid >> 6;

    {
        const int r = tid >> 2, c4 = tid & 3;
        const float4* src = (const float4*)(g_Q + (size_t)(t0 + r) * 64 + c4 * 16);
        #pragma unroll
        for (int q = 0; q < 4; q++) {
            float4 v = src[q];
            int d0 = c4 * 16 + q * 4;
            Qs[r * 65 + d0 + 0] = v.x;
            Qs[r * 65 + d0 + 1] = v.y;
            Qs[r * 65 + d0 + 2] = v.z;
            Qs[r * 65 + d0 + 3] = v.w;
        }
    }

    const int idx = g_idx[(size_t)m * TT + t0 + lt];
    __syncthreads();

    float a0 = 0.0f, a1 = 0.0f;
    if (idx >= 0) {
        const float2* sp = (const float2*)g_S + (size_t)(m * 64 + dq * 16) * TT + idx;
        #pragma unroll
        for (int dd = 0; dd < 16; dd++) {
            float q  = Qs[lt * 65 + dq * 16 + dd];
            float2 s = sp[(size_t)dd * TT];
            a0 += q * s.x;
            a1 += q * s.y;
        }
    }
    red[tid] = make_float2(a0, a1);
    __syncthreads();

    if (dq == 0) {
        float ax = 0.0f, ay = 0.0f;
        #pragma unroll
        for (int q = 0; q < 4; q++) {
            float2 v = red[lt + 64 * q];
            ax += v.x; ay += v.y;
        }
        atomicAdd(out + (size_t)(t0 + lt) * 2 + 0, ax);
        atomicAdd(out + (size_t)(t0 + lt) * 2 + 1, ay);
    }
}

// ---------------- launch ----------------
extern "C" void kernel_launch(void* const* d_in, const int* in_sizes, int n_in,
                              void* d_out, int out_size)
{
    const float* X    = (const float*)d_in[0];
    const float* wq_w = (const float*)d_in[1];
    const float* wq_b = (const float*)d_in[2];
    const float* wk_w = (const float*)d_in[3];
    const float* wk_b = (const float*)d_in[4];
    float* out = (float*)d_out;

    cudaFuncSetAttribute(k_mlp, cudaFuncAttributeMaxDynamicSharedMemorySize, MLP_SMEM);

    k_mlp    <<<dim3(TT / 128, 5), 256, MLP_SMEM>>>(X, wq_w, wq_b, wk_w, wk_b);
    k_scanIdx<<<512 + 128, 256>>>(out);
    k_gath   <<<dim3(TT / 64, MM), 256>>>(out);
}